// round 13
// baseline (speedup 1.0000x reference)
#include <cuda_runtime.h>
#include <cuda_fp16.h>
#include <cstdint>

#define BB 4
#define NF 128
#define NK 64
#define NV 64
#define LL 4096
#define TQ 128
#define TL 128
#define NT (LL / TL)

// all attn tiles: 128 rows x 64 x 2B, row pitch 144B
#define ROWB 144
#define TILESZ 18432

#define OFF_HQ 0
#define OFF_FKB TILESZ                        // 2 bufs
#define FKBUFSZ TILESZ
#define OFF_FVB (OFF_FKB + 2 * FKBUFSZ)       // 2 bufs
#define FVBUFSZ TILESZ
#define OFF_DEN (OFF_FVB + 2 * FVBUFSZ)       // float[2][128]
#define SMEM_ATTN (OFF_DEN + 1024)            // 93184
#define OFF_YS OFF_FKB                        // reuse post-loop: float[128][68]

// ---- proj smem ----
#define WPITCH 132
#define WTILE (64 * WPITCH * 4)
#define OFF_WH 0
#define OFF_WL WTILE
#define OFF_BS (2 * WTILE)
#define STGPITCH 260
#define SMEM_PROJ (2 * WTILE + 512)

#define ONES2 0x3C003C00u   // f16x2 (1.0, 1.0)

// projection outputs, all fp16 [b][row][64]:
// hq (pre-scaled by log2e/8), fk, fv
__device__ __align__(256) __half g_hq[BB * LL * NK];
__device__ __align__(256) __half g_fk[BB * LL * NK];
__device__ __align__(256) __half g_fv[BB * LL * NV];

// ---------------------------------------------------------------------------
__device__ __forceinline__ uint32_t smem_u32(const void* p) {
    uint32_t a;
    asm("{ .reg .u64 t; cvta.to.shared.u64 t, %1; cvt.u32.u64 %0, t; }"
        : "=r"(a) : "l"(p));
    return a;
}
__device__ __forceinline__ void cpasync16(uint32_t dst, const void* src) {
    asm volatile("cp.async.cg.shared.global [%0], [%1], 16;"
                 :: "r"(dst), "l"(src));
}
#define CP_COMMIT() asm volatile("cp.async.commit_group;")
#define CP_WAIT(n)  asm volatile("cp.async.wait_group %0;" :: "n"(n))

__device__ __forceinline__ void ldsm4(uint32_t* r, uint32_t a) {
    asm volatile("ldmatrix.sync.aligned.m8n8.x4.shared.b16 {%0,%1,%2,%3}, [%4];"
        : "=r"(r[0]), "=r"(r[1]), "=r"(r[2]), "=r"(r[3]) : "r"(a));
}
__device__ __forceinline__ void ldsm4t(uint32_t* r, uint32_t a) {
    asm volatile("ldmatrix.sync.aligned.m8n8.x4.trans.shared.b16 {%0,%1,%2,%3}, [%4];"
        : "=r"(r[0]), "=r"(r[1]), "=r"(r[2]), "=r"(r[3]) : "r"(a));
}
// fp16 MMA
__device__ __forceinline__ void mma16816f(
    float* d, const uint32_t* a, uint32_t b0, uint32_t b1)
{
    asm volatile(
        "mma.sync.aligned.m16n8k16.row.col.f32.f16.f16.f32 "
        "{%0,%1,%2,%3}, {%4,%5,%6,%7}, {%8,%9}, {%0,%1,%2,%3};"
        : "+f"(d[0]), "+f"(d[1]), "+f"(d[2]), "+f"(d[3])
        : "r"(a[0]), "r"(a[1]), "r"(a[2]), "r"(a[3]), "r"(b0), "r"(b1));
}
// tf32 MMA (proj only)
__device__ __forceinline__ void mma1688(
    float* d, const uint32_t* a, uint32_t b0, uint32_t b1)
{
    asm volatile(
        "mma.sync.aligned.m16n8k8.row.col.f32.tf32.tf32.f32 "
        "{%0,%1,%2,%3}, {%4,%5,%6,%7}, {%8,%9}, {%0,%1,%2,%3};"
        : "+f"(d[0]), "+f"(d[1]), "+f"(d[2]), "+f"(d[3])
        : "r"(a[0]), "r"(a[1]), "r"(a[2]), "r"(a[3]), "r"(b0), "r"(b1));
}
__device__ __forceinline__ uint32_t to_tf32(float x) {
    uint32_t r;
    asm("cvt.rna.tf32.f32 %0, %1;" : "=r"(r) : "f"(x));
    return r;
}
__device__ __forceinline__ uint32_t packf16(float x0, float x1) {
    uint32_t p;
    asm("cvt.rn.f16x2.f32 %0, %1, %2;" : "=r"(p) : "f"(x1), "f"(x0));
    return p;
}
__device__ __forceinline__ uint32_t ex2h2(uint32_t x) {
    uint32_t r;
    asm("ex2.approx.f16x2 %0, %1;" : "=r"(r) : "r"(x));
    return r;
}

// ---------------------------------------------------------------------------
// Kernel A: projections via tf32 tensor cores (3-term hi/lo split).
// All outputs fp16: z=0 fk, z=1 fv, z=2 hq (scaled log2e/8).
// ---------------------------------------------------------------------------
__global__ __launch_bounds__(256) void proj_kernel(
    const float* __restrict__ field, const float* __restrict__ query,
    const float* __restrict__ W_fk, const float* __restrict__ b_fk,
    const float* __restrict__ W_fv, const float* __restrict__ b_fv,
    const float* __restrict__ W_qk, const float* __restrict__ b_qk)
{
    extern __shared__ __align__(16) char psm[];
    float* Wh = (float*)(psm + OFF_WH);
    float* Wl = (float*)(psm + OFF_WL);
    float* bs = (float*)(psm + OFF_BS);

    const int z = blockIdx.z, b = blockIdx.y;
    const int tid = threadIdx.x, lane = tid & 31, warp = tid >> 5;
    const int gid = lane >> 2, tig = lane & 3;

    const float *W, *bias, *X;
    switch (z) {
        case 0:  W = W_fk; bias = b_fk; X = field; break;
        case 1:  W = W_fv; bias = b_fv; X = field; break;
        default: W = W_qk; bias = b_qk; X = query; break;
    }

    for (int i = tid; i < NK * NF; i += 256) {
        float w = W[i];
        uint32_t h = to_tf32(w);
        float hf = __uint_as_float(h);
        int k = i >> 7, c = i & 127;
        Wh[k * WPITCH + c] = hf;
        Wl[k * WPITCH + c] = __uint_as_float(to_tf32(w - hf));
    }
    if (tid < NK) bs[tid] = bias[tid];
    __syncthreads();

    const int l0 = blockIdx.x * 256 + warp * 32;
    const uint32_t sbW = smem_u32(psm);
    const uint32_t abase =
        (uint32_t)((((lane >> 3) & 1) * 8 + (lane & 7)) * WPITCH) * 4 +
        (uint32_t)(lane >> 4) * 16;

    float acc[4][4][4];
    #pragma unroll
    for (int mt = 0; mt < 4; mt++)
        #pragma unroll
        for (int ng = 0; ng < 4; ng++)
            #pragma unroll
            for (int i = 0; i < 4; i++) acc[mt][ng][i] = 0.f;

    const float* Xb = X + (size_t)b * NF * LL;

    #pragma unroll 4
    for (int ch = 0; ch < 16; ch++) {
        uint32_t Ah[4][4], Al[4][4];
        #pragma unroll
        for (int mt = 0; mt < 4; mt++) {
            ldsm4(Ah[mt], sbW + OFF_WH + abase + mt * (16 * WPITCH * 4) + ch * 32);
            ldsm4(Al[mt], sbW + OFF_WL + abase + mt * (16 * WPITCH * 4) + ch * 32);
        }
        #pragma unroll
        for (int ng = 0; ng < 4; ng++) {
            const float* xp = Xb + (size_t)(ch * 8 + tig) * LL + l0 + ng * 8 + gid;
            float x0 = xp[0];
            float x1 = xp[4 * LL];
            uint32_t b0h = to_tf32(x0);
            uint32_t b0l = to_tf32(x0 - __uint_as_float(b0h));
            uint32_t b1h = to_tf32(x1);
            uint32_t b1l = to_tf32(x1 - __uint_as_float(b1h));
            #pragma unroll
            for (int mt = 0; mt < 4; mt++) {
                mma1688(acc[mt][ng], Ah[mt], b0h, b1h);
                mma1688(acc[mt][ng], Ah[mt], b0l, b1l);
                mma1688(acc[mt][ng], Al[mt], b0h, b1h);
            }
        }
    }

    #pragma unroll
    for (int mt = 0; mt < 4; mt++) {
        float bv0 = bs[mt * 16 + gid], bv1 = bs[mt * 16 + 8 + gid];
        #pragma unroll
        for (int ng = 0; ng < 4; ng++) {
            acc[mt][ng][0] += bv0; acc[mt][ng][1] += bv0;
            acc[mt][ng][2] += bv1; acc[mt][ng][3] += bv1;
        }
    }

    // ---- stage through smem, pack fp16, vectorized store ----
    __syncthreads();             // done reading W
    float* stg = (float*)psm;    // [64 k][STGPITCH l]
    #pragma unroll
    for (int mt = 0; mt < 4; mt++)
        #pragma unroll
        for (int ng = 0; ng < 4; ng++) {
            int lc = warp * 32 + ng * 8 + 2 * tig;
            int k = mt * 16 + gid;
            stg[k * STGPITCH + lc]           = acc[mt][ng][0];
            stg[k * STGPITCH + lc + 1]       = acc[mt][ng][1];
            stg[(k + 8) * STGPITCH + lc]     = acc[mt][ng][2];
            stg[(k + 8) * STGPITCH + lc + 1] = acc[mt][ng][3];
        }
    __syncthreads();
    int l = blockIdx.x * 256 + tid;
    // fold 1/sqrt(64) and log2(e) into hq
    const float sc = (z == 2) ? 0.125f * 1.44269504088896f : 1.0f;
    uint32_t hw[32];
    #pragma unroll
    for (int j = 0; j < 32; j++)
        hw[j] = packf16(sc * stg[(2 * j) * STGPITCH + tid],
                        sc * stg[(2 * j + 1) * STGPITCH + tid]);
    __half* dh = (z == 0 ? g_fk : (z == 1 ? g_fv : g_hq)) +
                 ((size_t)b * LL + l) * NK;
    #pragma unroll
    for (int i = 0; i < 8; i++) ((uint4*)dh)[i] = ((uint4*)hw)[i];
}

// ---------------------------------------------------------------------------
// Kernel B: flash attention, all-fp16 MMA path. 512 threads, 16 warps
// (4/SMSP for latency hiding): wr = warp>>1 (16 q-rows), wc = warp&1
// (64 l-cols). Epilogue: f16x2 ex2; denominator via ones-column MMA.
// ---------------------------------------------------------------------------
__global__ __launch_bounds__(512, 1) void attn_kernel(float* __restrict__ out)
{
    extern __shared__ __align__(16) char sm[];
    const uint32_t sb = smem_u32(sm);

    const int tid = threadIdx.x;
    const int lane = tid & 31, warp = tid >> 5;
    const int gid = lane >> 2, tig = lane & 3;
    const int wc = warp & 1, wr = warp >> 1;
    const int qw = wr * 16;
    const int b = blockIdx.y;
    const int qbase = blockIdx.x * TQ;

    const uint32_t aoff =
        (uint32_t)(qw + ((lane >> 3) & 1) * 8 + (lane & 7)) * ROWB +
        (uint32_t)(lane >> 4) * 16;
    const uint32_t b1off =
        (uint32_t)(wc * 64 + ((lane >> 3) & 1) * 8 + (lane & 7)) * ROWB +
        (uint32_t)(lane >> 4) * 16;
    const uint32_t b2off =
        (uint32_t)(wc * 64 + (lane >> 4) * 8 + (lane & 7)) * ROWB +
        (uint32_t)((lane >> 3) & 1) * 16;

    const __half* hq_g = g_hq + ((size_t)b * LL + qbase) * NK;
    const __half* fk_g = g_fk + (size_t)b * LL * NK;
    const __half* fv_g = g_fv + (size_t)b * LL * NV;

    // ---- prologue: hq tile + field tile 0 ----
    for (int i = tid; i < 1024; i += 512) {
        int row = i >> 3, c = i & 7;
        cpasync16(sb + OFF_HQ + row * ROWB + c * 16, hq_g + row * NK + c * 8);
        cpasync16(sb + OFF_FKB + row * ROWB + c * 16, fk_g + row * NK + c * 8);
        cpasync16(sb + OFF_FVB + row * ROWB + c * 16, fv_g + row * NV + c * 8);
    }
    CP_COMMIT();

    float y[8][4];
    #pragma unroll
    for (int j = 0; j < 8; j++)
        #pragma unroll
        for (int i = 0; i < 4; i++) y[j][i] = 0.f;
    float dnacc[4] = {0.f, 0.f, 0.f, 0.f};

    for (int t = 0; t < NT; ++t) {
        if (t + 1 < NT) {
            __syncthreads();
            int buf = (t + 1) & 1;
            const __half* fkt = fk_g + (size_t)(t + 1) * TL * NK;
            const __half* fvt = fv_g + (size_t)(t + 1) * TL * NV;
            for (int i = tid; i < 1024; i += 512) {
                int row = i >> 3, c = i & 7;
                cpasync16(sb + OFF_FKB + buf * FKBUFSZ + row * ROWB + c * 16,
                          fkt + row * NK + c * 8);
                cpasync16(sb + OFF_FVB + buf * FVBUFSZ + row * ROWB + c * 16,
                          fvt + row * NV + c * 8);
            }
            CP_COMMIT();
            CP_WAIT(1);
        } else {
            CP_WAIT(0);
        }
        __syncthreads();

        const int buf = t & 1;
        const uint32_t hq_b = sb + OFF_HQ + aoff;
        const uint32_t fk_b = sb + OFF_FKB + buf * FKBUFSZ + b1off;
        const uint32_t fv_b = sb + OFF_FVB + buf * FVBUFSZ + b2off;

        // ---- MMA1 (fp16): S[16 q][64 l], K = 64 (4 k16 chunks) ----
        float s[8][4];
        #pragma unroll
        for (int j = 0; j < 8; j++)
            #pragma unroll
            for (int i = 0; i < 4; i++) s[j][i] = 0.f;

        #pragma unroll
        for (int c = 0; c < 4; c++) {
            uint32_t A[4];
            ldsm4(A, hq_b + c * 32);
            #pragma unroll
            for (int jj = 0; jj < 4; jj++) {
                uint32_t Bk[4];
                ldsm4(Bk, fk_b + jj * (16 * ROWB) + c * 32);
                mma16816f(s[2 * jj],     A, Bk[0], Bk[2]);
                mma16816f(s[2 * jj + 1], A, Bk[1], Bk[3]);
            }
        }

        // ---- epilogue: w = exp2(s) via f16x2, packed as A-fragments ----
        uint32_t wf[8][2];
        #pragma unroll
        for (int j = 0; j < 8; j++) {
            wf[j][0] = ex2h2(packf16(s[j][0], s[j][1]));
            wf[j][1] = ex2h2(packf16(s[j][2], s[j][3]));
        }

        // ---- MMA2 (fp16): Y[16 q][64 v] += w * fv; denom via ones-MMA ----
        #pragma unroll
        for (int cc = 0; cc < 4; cc++) {
            uint32_t W0[4] = { wf[2 * cc][0], wf[2 * cc][1],
                               wf[2 * cc + 1][0], wf[2 * cc + 1][1] };
            mma16816f(dnacc, W0, ONES2, ONES2);
            #pragma unroll
            for (int jj = 0; jj < 4; jj++) {
                uint32_t Vh[4];
                ldsm4t(Vh, fv_b + cc * (16 * ROWB) + jj * 32);
                mma16816f(y[2 * jj],     W0, Vh[0], Vh[2]);
                mma16816f(y[2 * jj + 1], W0, Vh[1], Vh[3]);
            }
        }
    }

    // ---- final reductions ----
    __syncthreads();  // done with fk buffers (ysf aliases them)

    float* den = (float*)(sm + OFF_DEN);
    if (tig == 0) {
        den[wc * 128 + qw + gid]     = dnacc[0];
        den[wc * 128 + qw + 8 + gid] = dnacc[2];
    }

    float* ysf = (float*)(sm + OFF_YS);  // [128 q][68]
    if (wc == 0) {
        #pragma unroll
        for (int j = 0; j < 8; j++)
            #pragma unroll
            for (int i = 0; i < 4; i++) {
                int q = qw + gid + (i >> 1) * 8;
                int v = 8 * j + 2 * tig + (i & 1);
                ysf[q * 68 + v] = y[j][i];
            }
    }
    __syncthreads();
    if (wc == 1) {
        #pragma unroll
        for (int j = 0; j < 8; j++)
            #pragma unroll
            for (int i = 0; i < 4; i++) {
                int q = qw + gid + (i >> 1) * 8;
                int v = 8 * j + 2 * tig + (i & 1);
                ysf[q * 68 + v] += y[j][i];
            }
    }
    __syncthreads();
    if (tid < 128)
        den[tid] = 1.0f / (den[tid] + den[128 + tid] + 1e-16f);
    __syncthreads();

    #pragma unroll
    for (int it = 0; it < 16; it++) {
        int idx = tid + it * 512;
        int v = idx >> 7, q = idx & 127;
        out[((size_t)b * NV + v) * LL + qbase + q] = ysf[q * 68 + v] * den[q];
    }
}

// ---------------------------------------------------------------------------
extern "C" void kernel_launch(void* const* d_in, const int* in_sizes, int n_in,
                              void* d_out, int out_size)
{
    const float* field = (const float*)d_in[0];
    const float* query = (const float*)d_in[1];
    const float* W_fk  = (const float*)d_in[2];
    const float* b_fk  = (const float*)d_in[3];
    const float* W_fv  = (const float*)d_in[4];
    const float* b_fv  = (const float*)d_in[5];
    const float* W_qk  = (const float*)d_in[6];
    const float* b_qk  = (const float*)d_in[7];
    float* out = (float*)d_out;

    static int configured = 0;
    if (!configured) {
        cudaFuncSetAttribute(attn_kernel,
                             cudaFuncAttributeMaxDynamicSharedMemorySize,
                             SMEM_ATTN);
        cudaFuncSetAttribute(proj_kernel,
                             cudaFuncAttributeMaxDynamicSharedMemorySize,
                             SMEM_PROJ);
        configured = 1;
    }

    dim3 gproj(LL / 256, BB, 3);
    proj_kernel<<<gproj, 256, SMEM_PROJ>>>(field, query, W_fk, b_fk,
                                           W_fv, b_fv, W_qk, b_qk);

    dim3 gattn(LL / TQ, BB);  // 32 x 4 = 128 CTAs
    attn_kernel<<<gattn, 512, SMEM_ATTN>>>(out);
}

// round 14
// speedup vs baseline: 1.0560x; 1.0560x over previous
#include <cuda_runtime.h>
#include <cuda_fp16.h>
#include <cstdint>

#define BB 4
#define NF 128
#define NK 64
#define NV 64
#define LL 4096
#define TQ 128
#define TL 128
#define NT (LL / TL)

// all attn tiles: 128 rows x 64 x 2B, row pitch 144B
#define ROWB 144
#define TILESZ 18432

#define OFF_HQ 0
#define OFF_FKB TILESZ                        // 2 bufs
#define FKBUFSZ TILESZ
#define OFF_FVB (OFF_FKB + 2 * FKBUFSZ)       // 2 bufs
#define FVBUFSZ TILESZ
#define OFF_DEN (OFF_FVB + 2 * FVBUFSZ)       // float[2][128]
#define SMEM_ATTN (OFF_DEN + 1024)            // 93184
#define OFF_YS OFF_FKB                        // reuse post-loop: float[128][68]

// ---- proj smem ----
#define WPITCH 132
#define WTILE (64 * WPITCH * 4)
#define OFF_BS WTILE
#define STGPITCH 260
#define SMEM_PROJ (2 * WTILE + 512)   // staging needs 64*260*4 = 66560

#define ONES2 0x3C003C00u   // f16x2 (1.0, 1.0)

// projection outputs, all fp16 [b][row][64]:
// hq (pre-scaled by log2e/8), fk, fv
__device__ __align__(256) __half g_hq[BB * LL * NK];
__device__ __align__(256) __half g_fk[BB * LL * NK];
__device__ __align__(256) __half g_fv[BB * LL * NV];

// ---------------------------------------------------------------------------
__device__ __forceinline__ uint32_t smem_u32(const void* p) {
    uint32_t a;
    asm("{ .reg .u64 t; cvta.to.shared.u64 t, %1; cvt.u32.u64 %0, t; }"
        : "=r"(a) : "l"(p));
    return a;
}
__device__ __forceinline__ void cpasync16(uint32_t dst, const void* src) {
    asm volatile("cp.async.cg.shared.global [%0], [%1], 16;"
                 :: "r"(dst), "l"(src));
}
#define CP_COMMIT() asm volatile("cp.async.commit_group;")
#define CP_WAIT(n)  asm volatile("cp.async.wait_group %0;" :: "n"(n))

__device__ __forceinline__ void ldsm4(uint32_t* r, uint32_t a) {
    asm volatile("ldmatrix.sync.aligned.m8n8.x4.shared.b16 {%0,%1,%2,%3}, [%4];"
        : "=r"(r[0]), "=r"(r[1]), "=r"(r[2]), "=r"(r[3]) : "r"(a));
}
__device__ __forceinline__ void ldsm4t(uint32_t* r, uint32_t a) {
    asm volatile("ldmatrix.sync.aligned.m8n8.x4.trans.shared.b16 {%0,%1,%2,%3}, [%4];"
        : "=r"(r[0]), "=r"(r[1]), "=r"(r[2]), "=r"(r[3]) : "r"(a));
}
// fp16 MMA
__device__ __forceinline__ void mma16816f(
    float* d, const uint32_t* a, uint32_t b0, uint32_t b1)
{
    asm volatile(
        "mma.sync.aligned.m16n8k16.row.col.f32.f16.f16.f32 "
        "{%0,%1,%2,%3}, {%4,%5,%6,%7}, {%8,%9}, {%0,%1,%2,%3};"
        : "+f"(d[0]), "+f"(d[1]), "+f"(d[2]), "+f"(d[3])
        : "r"(a[0]), "r"(a[1]), "r"(a[2]), "r"(a[3]), "r"(b0), "r"(b1));
}
// tf32 MMA (proj only)
__device__ __forceinline__ void mma1688(
    float* d, const uint32_t* a, uint32_t b0, uint32_t b1)
{
    asm volatile(
        "mma.sync.aligned.m16n8k8.row.col.f32.tf32.tf32.f32 "
        "{%0,%1,%2,%3}, {%4,%5,%6,%7}, {%8,%9}, {%0,%1,%2,%3};"
        : "+f"(d[0]), "+f"(d[1]), "+f"(d[2]), "+f"(d[3])
        : "r"(a[0]), "r"(a[1]), "r"(a[2]), "r"(a[3]), "r"(b0), "r"(b1));
}
__device__ __forceinline__ uint32_t to_tf32(float x) {
    uint32_t r;
    asm("cvt.rna.tf32.f32 %0, %1;" : "=r"(r) : "f"(x));
    return r;
}
__device__ __forceinline__ uint32_t packf16(float x0, float x1) {
    uint32_t p;
    asm("cvt.rn.f16x2.f32 %0, %1, %2;" : "=r"(p) : "f"(x1), "f"(x0));
    return p;
}
__device__ __forceinline__ uint32_t ex2h2(uint32_t x) {
    uint32_t r;
    asm("ex2.approx.f16x2 %0, %1;" : "=r"(r) : "r"(x));
    return r;
}

// ---------------------------------------------------------------------------
// Kernel A: projections via tf32 tensor cores (single-term — error below
// the fp16 output quantization). z=0 fk, z=1 fv, z=2 hq (scaled log2e/8).
// ---------------------------------------------------------------------------
__global__ __launch_bounds__(256) void proj_kernel(
    const float* __restrict__ field, const float* __restrict__ query,
    const float* __restrict__ W_fk, const float* __restrict__ b_fk,
    const float* __restrict__ W_fv, const float* __restrict__ b_fv,
    const float* __restrict__ W_qk, const float* __restrict__ b_qk)
{
    extern __shared__ __align__(16) char psm[];
    float* Wh = (float*)psm;
    float* bs = (float*)(psm + OFF_BS);

    const int z = blockIdx.z, b = blockIdx.y;
    const int tid = threadIdx.x, lane = tid & 31, warp = tid >> 5;
    const int gid = lane >> 2, tig = lane & 3;

    const float *W, *bias, *X;
    switch (z) {
        case 0:  W = W_fk; bias = b_fk; X = field; break;
        case 1:  W = W_fv; bias = b_fv; X = field; break;
        default: W = W_qk; bias = b_qk; X = query; break;
    }

    for (int i = tid; i < NK * NF; i += 256) {
        int k = i >> 7, c = i & 127;
        Wh[k * WPITCH + c] = __uint_as_float(to_tf32(W[i]));
    }
    if (tid < NK) bs[tid] = bias[tid];
    __syncthreads();

    const int l0 = blockIdx.x * 256 + warp * 32;
    const uint32_t sbW = smem_u32(psm);
    const uint32_t abase =
        (uint32_t)((((lane >> 3) & 1) * 8 + (lane & 7)) * WPITCH) * 4 +
        (uint32_t)(lane >> 4) * 16;

    float acc[4][4][4];
    #pragma unroll
    for (int mt = 0; mt < 4; mt++)
        #pragma unroll
        for (int ng = 0; ng < 4; ng++)
            #pragma unroll
            for (int i = 0; i < 4; i++) acc[mt][ng][i] = 0.f;

    const float* Xb = X + (size_t)b * NF * LL;

    #pragma unroll 4
    for (int ch = 0; ch < 16; ch++) {
        uint32_t Ah[4][4];
        #pragma unroll
        for (int mt = 0; mt < 4; mt++)
            ldsm4(Ah[mt], sbW + abase + mt * (16 * WPITCH * 4) + ch * 32);
        #pragma unroll
        for (int ng = 0; ng < 4; ng++) {
            const float* xp = Xb + (size_t)(ch * 8 + tig) * LL + l0 + ng * 8 + gid;
            uint32_t b0 = to_tf32(xp[0]);
            uint32_t b1 = to_tf32(xp[4 * LL]);
            #pragma unroll
            for (int mt = 0; mt < 4; mt++)
                mma1688(acc[mt][ng], Ah[mt], b0, b1);
        }
    }

    #pragma unroll
    for (int mt = 0; mt < 4; mt++) {
        float bv0 = bs[mt * 16 + gid], bv1 = bs[mt * 16 + 8 + gid];
        #pragma unroll
        for (int ng = 0; ng < 4; ng++) {
            acc[mt][ng][0] += bv0; acc[mt][ng][1] += bv0;
            acc[mt][ng][2] += bv1; acc[mt][ng][3] += bv1;
        }
    }

    // ---- stage through smem, pack fp16, vectorized store ----
    __syncthreads();             // done reading W
    float* stg = (float*)psm;    // [64 k][STGPITCH l]
    #pragma unroll
    for (int mt = 0; mt < 4; mt++)
        #pragma unroll
        for (int ng = 0; ng < 4; ng++) {
            int lc = warp * 32 + ng * 8 + 2 * tig;
            int k = mt * 16 + gid;
            stg[k * STGPITCH + lc]           = acc[mt][ng][0];
            stg[k * STGPITCH + lc + 1]       = acc[mt][ng][1];
            stg[(k + 8) * STGPITCH + lc]     = acc[mt][ng][2];
            stg[(k + 8) * STGPITCH + lc + 1] = acc[mt][ng][3];
        }
    __syncthreads();
    int l = blockIdx.x * 256 + tid;
    // fold 1/sqrt(64) and log2(e) into hq
    const float sc = (z == 2) ? 0.125f * 1.44269504088896f : 1.0f;
    uint32_t hw[32];
    #pragma unroll
    for (int j = 0; j < 32; j++)
        hw[j] = packf16(sc * stg[(2 * j) * STGPITCH + tid],
                        sc * stg[(2 * j + 1) * STGPITCH + tid]);
    __half* dh = (z == 0 ? g_fk : (z == 1 ? g_fv : g_hq)) +
                 ((size_t)b * LL + l) * NK;
    #pragma unroll
    for (int i = 0; i < 8; i++) ((uint4*)dh)[i] = ((uint4*)hw)[i];
}

// ---------------------------------------------------------------------------
// Kernel B: flash attention, all-fp16, software-pipelined across tiles:
// iteration t does exp(s_t) -> MMA1(t+1) -> MMA2(t), so exp never waits on
// an in-flight MMA and the tensor pipe sees a continuous HMMA stream.
// 256 threads, 8 warps: wr = warp>>1 (32 q-rows), wc = warp&1 (64 l-cols).
// ---------------------------------------------------------------------------
__global__ __launch_bounds__(256, 1) void attn_kernel(float* __restrict__ out)
{
    extern __shared__ __align__(16) char sm[];
    const uint32_t sb = smem_u32(sm);

    const int tid = threadIdx.x;
    const int lane = tid & 31, warp = tid >> 5;
    const int gid = lane >> 2, tig = lane & 3;
    const int wc = warp & 1, wr = warp >> 1;
    const int qw = wr * 32;
    const int b = blockIdx.y;
    const int qbase = blockIdx.x * TQ;

    const uint32_t aoff =
        (uint32_t)(qw + ((lane >> 3) & 1) * 8 + (lane & 7)) * ROWB +
        (uint32_t)(lane >> 4) * 16;
    const uint32_t b1off =
        (uint32_t)(wc * 64 + ((lane >> 3) & 1) * 8 + (lane & 7)) * ROWB +
        (uint32_t)(lane >> 4) * 16;
    const uint32_t b2off =
        (uint32_t)(wc * 64 + (lane >> 4) * 8 + (lane & 7)) * ROWB +
        (uint32_t)((lane >> 3) & 1) * 16;

    const __half* hq_g = g_hq + ((size_t)b * LL + qbase) * NK;
    const __half* fk_g = g_fk + (size_t)b * LL * NK;
    const __half* fv_g = g_fv + (size_t)b * LL * NV;

    // ---- prologue: G0 = {hq, fk0, fv0} -> buf0 ; G1 = {fk1, fv1} -> buf1
    for (int i = tid; i < 1024; i += 256) {
        int row = i >> 3, c = i & 7;
        cpasync16(sb + OFF_HQ + row * ROWB + c * 16, hq_g + row * NK + c * 8);
        cpasync16(sb + OFF_FKB + row * ROWB + c * 16, fk_g + row * NK + c * 8);
        cpasync16(sb + OFF_FVB + row * ROWB + c * 16, fv_g + row * NV + c * 8);
    }
    CP_COMMIT();
    for (int i = tid; i < 1024; i += 256) {
        int row = i >> 3, c = i & 7;
        cpasync16(sb + OFF_FKB + FKBUFSZ + row * ROWB + c * 16,
                  fk_g + (size_t)TL * NK + row * NK + c * 8);
        cpasync16(sb + OFF_FVB + FVBUFSZ + row * ROWB + c * 16,
                  fv_g + (size_t)TL * NV + row * NV + c * 8);
    }
    CP_COMMIT();

    const uint32_t hq_b = sb + OFF_HQ + aoff;

    float y[2][8][4];
    #pragma unroll
    for (int m = 0; m < 2; m++)
        #pragma unroll
        for (int j = 0; j < 8; j++)
            #pragma unroll
            for (int i = 0; i < 4; i++) y[m][j][i] = 0.f;
    float dnacc[2][4];
    #pragma unroll
    for (int m = 0; m < 2; m++)
        #pragma unroll
        for (int i = 0; i < 4; i++) dnacc[m][i] = 0.f;

    float s[2][8][4];

    // ---- MMA1(tile 0) in prologue ----
    CP_WAIT(1);
    __syncthreads();
    {
        #pragma unroll
        for (int m = 0; m < 2; m++)
            #pragma unroll
            for (int j = 0; j < 8; j++)
                #pragma unroll
                for (int i = 0; i < 4; i++) s[m][j][i] = 0.f;
        const uint32_t fk_b = sb + OFF_FKB + b1off;
        #pragma unroll
        for (int c = 0; c < 4; c++) {
            uint32_t A0[4], A1[4];
            ldsm4(A0, hq_b + c * 32);
            ldsm4(A1, hq_b + 16 * ROWB + c * 32);
            #pragma unroll
            for (int jj = 0; jj < 4; jj++) {
                uint32_t Bk[4];
                ldsm4(Bk, fk_b + jj * (16 * ROWB) + c * 32);
                mma16816f(s[0][2 * jj],     A0, Bk[0], Bk[2]);
                mma16816f(s[0][2 * jj + 1], A0, Bk[1], Bk[3]);
                mma16816f(s[1][2 * jj],     A1, Bk[0], Bk[2]);
                mma16816f(s[1][2 * jj + 1], A1, Bk[1], Bk[3]);
            }
        }
    }

    for (int t = 0; t < NT; ++t) {
        // ---- epilogue of tile t: w = exp2(s) (s completed last iter) ----
        uint32_t wf[2][8][2];
        #pragma unroll
        for (int m = 0; m < 2; m++)
            #pragma unroll
            for (int j = 0; j < 8; j++) {
                wf[m][j][0] = ex2h2(packf16(s[m][j][0], s[m][j][1]));
                wf[m][j][1] = ex2h2(packf16(s[m][j][2], s[m][j][3]));
            }

        // ---- MMA1(t+1) from the other buffer ----
        if (t + 1 < NT) {
            CP_WAIT(0);       // pending = {G(t+1)} only
            __syncthreads();
            #pragma unroll
            for (int m = 0; m < 2; m++)
                #pragma unroll
                for (int j = 0; j < 8; j++)
                    #pragma unroll
                    for (int i = 0; i < 4; i++) s[m][j][i] = 0.f;
            const uint32_t fk_b = sb + OFF_FKB + ((t + 1) & 1) * FKBUFSZ + b1off;
            #pragma unroll
            for (int c = 0; c < 4; c++) {
                uint32_t A0[4], A1[4];
                ldsm4(A0, hq_b + c * 32);
                ldsm4(A1, hq_b + 16 * ROWB + c * 32);
                #pragma unroll
                for (int jj = 0; jj < 4; jj++) {
                    uint32_t Bk[4];
                    ldsm4(Bk, fk_b + jj * (16 * ROWB) + c * 32);
                    mma16816f(s[0][2 * jj],     A0, Bk[0], Bk[2]);
                    mma16816f(s[0][2 * jj + 1], A0, Bk[1], Bk[3]);
                    mma16816f(s[1][2 * jj],     A1, Bk[0], Bk[2]);
                    mma16816f(s[1][2 * jj + 1], A1, Bk[1], Bk[3]);
                }
            }
        }

        // ---- MMA2(t): Y += w * fv; denom via ones-MMA ----
        {
            const uint32_t fv_b = sb + OFF_FVB + (t & 1) * FVBUFSZ + b2off;
            #pragma unroll
            for (int cc = 0; cc < 4; cc++) {
                uint32_t W0[4] = { wf[0][2 * cc][0], wf[0][2 * cc][1],
                                   wf[0][2 * cc + 1][0], wf[0][2 * cc + 1][1] };
                uint32_t W1[4] = { wf[1][2 * cc][0], wf[1][2 * cc][1],
                                   wf[1][2 * cc + 1][0], wf[1][2 * cc + 1][1] };
                mma16816f(dnacc[0], W0, ONES2, ONES2);
                mma16816f(dnacc[1], W1, ONES2, ONES2);
                #pragma unroll
                for (int jj = 0; jj < 4; jj++) {
                    uint32_t Vh[4];
                    ldsm4t(Vh, fv_b + cc * (16 * ROWB) + jj * 32);
                    mma16816f(y[0][2 * jj],     W0, Vh[0], Vh[2]);
                    mma16816f(y[0][2 * jj + 1], W0, Vh[1], Vh[3]);
                    mma16816f(y[1][2 * jj],     W1, Vh[0], Vh[2]);
                    mma16816f(y[1][2 * jj + 1], W1, Vh[1], Vh[3]);
                }
            }
        }

        __syncthreads();   // all warps done reading buf t&1
        if (t + 2 < NT) {
            const __half* fkt = fk_g + (size_t)(t + 2) * TL * NK;
            const __half* fvt = fv_g + (size_t)(t + 2) * TL * NV;
            const uint32_t dkb = sb + OFF_FKB + (t & 1) * FKBUFSZ;
            const uint32_t dvb = sb + OFF_FVB + (t & 1) * FVBUFSZ;
            for (int i = tid; i < 1024; i += 256) {
                int row = i >> 3, c = i & 7;
                cpasync16(dkb + row * ROWB + c * 16, fkt + row * NK + c * 8);
                cpasync16(dvb + row * ROWB + c * 16, fvt + row * NV + c * 8);
            }
            CP_COMMIT();
        }
    }

    // ---- final reductions ----
    float* den = (float*)(sm + OFF_DEN);
    if (tig == 0) {
        #pragma unroll
        for (int m = 0; m < 2; m++) {
            den[wc * 128 + qw + m * 16 + gid]     = dnacc[m][0];
            den[wc * 128 + qw + m * 16 + 8 + gid] = dnacc[m][2];
        }
    }

    float* ysf = (float*)(sm + OFF_YS);  // [128 q][68]
    if (wc == 0) {
        #pragma unroll
        for (int m = 0; m < 2; m++)
            #pragma unroll
            for (int j = 0; j < 8; j++)
                #pragma unroll
                for (int i = 0; i < 4; i++) {
                    int q = qw + m * 16 + gid + (i >> 1) * 8;
                    int v = 8 * j + 2 * tig + (i & 1);
                    ysf[q * 68 + v] = y[m][j][i];
                }
    }
    __syncthreads();
    if (wc == 1) {
        #pragma unroll
        for (int m = 0; m < 2; m++)
            #pragma unroll
            for (int j = 0; j < 8; j++)
                #pragma unroll
                for (int i = 0; i < 4; i++) {
                    int q = qw + m * 16 + gid + (i >> 1) * 8;
                    int v = 8 * j + 2 * tig + (i & 1);
                    ysf[q * 68 + v] += y[m][j][i];
                }
    }
    __syncthreads();
    if (tid < 128)
        den[tid] = 1.0f / (den[tid] + den[128 + tid] + 1e-16f);
    __syncthreads();

    #pragma unroll
    for (int it = 0; it < 32; it++) {
        int idx = tid + it * 256;
        int v = idx >> 7, q = idx & 127;
        out[((size_t)b * NV + v) * LL + qbase + q] = ysf[q * 68 + v] * den[q];
    }
}

// ---------------------------------------------------------------------------
extern "C" void kernel_launch(void* const* d_in, const int* in_sizes, int n_in,
                              void* d_out, int out_size)
{
    const float* field = (const float*)d_in[0];
    const float* query = (const float*)d_in[1];
    const float* W_fk  = (const float*)d_in[2];
    const float* b_fk  = (const float*)d_in[3];
    const float* W_fv  = (const float*)d_in[4];
    const float* b_fv  = (const float*)d_in[5];
    const float* W_qk  = (const float*)d_in[6];
    const float* b_qk  = (const float*)d_in[7];
    float* out = (float*)d_out;

    static int configured = 0;
    if (!configured) {
        cudaFuncSetAttribute(attn_kernel,
                             cudaFuncAttributeMaxDynamicSharedMemorySize,
                             SMEM_ATTN);
        cudaFuncSetAttribute(proj_kernel,
                             cudaFuncAttributeMaxDynamicSharedMemorySize,
                             SMEM_PROJ);
        configured = 1;
    }

    dim3 gproj(LL / 256, BB, 3);
    proj_kernel<<<gproj, 256, SMEM_PROJ>>>(field, query, W_fk, b_fk,
                                           W_fv, b_fv, W_qk, b_qk);

    dim3 gattn(LL / TQ, BB);  // 32 x 4 = 128 CTAs
    attn_kernel<<<gattn, 256, SMEM_ATTN>>>(out);
}

// round 15
// speedup vs baseline: 1.0802x; 1.0229x over previous
#include <cuda_runtime.h>
#include <cuda_fp16.h>
#include <cstdint>

#define BB 4
#define NF 128
#define NK 64
#define NV 64
#define LL 4096
#define TQ 128
#define TL 128
#define NT (LL / TL)

// all attn tiles: 128 rows x 64 x 2B, row pitch 144B
#define ROWB 144
#define TILESZ 18432

#define OFF_HQ 0
#define OFF_FKB TILESZ                        // 3 bufs
#define OFF_FVB (OFF_FKB + 3 * TILESZ)        // 3 bufs
#define OFF_DEN (OFF_FVB + 3 * TILESZ)        // float[2][128]
#define SMEM_ATTN (OFF_DEN + 1024)            // 130048
#define OFF_YS OFF_FKB                        // reuse post-loop: float[128][68]

// ---- proj smem ----
#define WPITCH 132
#define WTILE (64 * WPITCH * 4)
#define OFF_BS WTILE
#define STGPITCH 260
#define SMEM_PROJ (2 * WTILE + 512)

#define ONES2 0x3C003C00u   // f16x2 (1.0, 1.0)

// projection outputs, all fp16 [b][row][64]:
// hq (pre-scaled by log2e/8), fk, fv
__device__ __align__(256) __half g_hq[BB * LL * NK];
__device__ __align__(256) __half g_fk[BB * LL * NK];
__device__ __align__(256) __half g_fv[BB * LL * NV];

// ---------------------------------------------------------------------------
__device__ __forceinline__ uint32_t smem_u32(const void* p) {
    uint32_t a;
    asm("{ .reg .u64 t; cvta.to.shared.u64 t, %1; cvt.u32.u64 %0, t; }"
        : "=r"(a) : "l"(p));
    return a;
}
__device__ __forceinline__ void cpasync16(uint32_t dst, const void* src) {
    asm volatile("cp.async.cg.shared.global [%0], [%1], 16;"
                 :: "r"(dst), "l"(src));
}
#define CP_COMMIT() asm volatile("cp.async.commit_group;")
#define CP_WAIT(n)  asm volatile("cp.async.wait_group %0;" :: "n"(n))

__device__ __forceinline__ void ldsm4(uint32_t* r, uint32_t a) {
    asm volatile("ldmatrix.sync.aligned.m8n8.x4.shared.b16 {%0,%1,%2,%3}, [%4];"
        : "=r"(r[0]), "=r"(r[1]), "=r"(r[2]), "=r"(r[3]) : "r"(a));
}
__device__ __forceinline__ void ldsm4t(uint32_t* r, uint32_t a) {
    asm volatile("ldmatrix.sync.aligned.m8n8.x4.trans.shared.b16 {%0,%1,%2,%3}, [%4];"
        : "=r"(r[0]), "=r"(r[1]), "=r"(r[2]), "=r"(r[3]) : "r"(a));
}
// fp16 MMA
__device__ __forceinline__ void mma16816f(
    float* d, const uint32_t* a, uint32_t b0, uint32_t b1)
{
    asm volatile(
        "mma.sync.aligned.m16n8k16.row.col.f32.f16.f16.f32 "
        "{%0,%1,%2,%3}, {%4,%5,%6,%7}, {%8,%9}, {%0,%1,%2,%3};"
        : "+f"(d[0]), "+f"(d[1]), "+f"(d[2]), "+f"(d[3])
        : "r"(a[0]), "r"(a[1]), "r"(a[2]), "r"(a[3]), "r"(b0), "r"(b1));
}
// tf32 MMA (proj only)
__device__ __forceinline__ void mma1688(
    float* d, const uint32_t* a, uint32_t b0, uint32_t b1)
{
    asm volatile(
        "mma.sync.aligned.m16n8k8.row.col.f32.tf32.tf32.f32 "
        "{%0,%1,%2,%3}, {%4,%5,%6,%7}, {%8,%9}, {%0,%1,%2,%3};"
        : "+f"(d[0]), "+f"(d[1]), "+f"(d[2]), "+f"(d[3])
        : "r"(a[0]), "r"(a[1]), "r"(a[2]), "r"(a[3]), "r"(b0), "r"(b1));
}
__device__ __forceinline__ uint32_t to_tf32(float x) {
    uint32_t r;
    asm("cvt.rna.tf32.f32 %0, %1;" : "=r"(r) : "f"(x));
    return r;
}
__device__ __forceinline__ uint32_t packf16(float x0, float x1) {
    uint32_t p;
    asm("cvt.rn.f16x2.f32 %0, %1, %2;" : "=r"(p) : "f"(x1), "f"(x0));
    return p;
}
__device__ __forceinline__ uint32_t ex2h2(uint32_t x) {
    uint32_t r;
    asm("ex2.approx.f16x2 %0, %1;" : "=r"(r) : "r"(x));
    return r;
}

// ---------------------------------------------------------------------------
// Kernel A: projections via single-term tf32 tensor cores (R14, unchanged).
// z=0 fk, z=1 fv, z=2 hq (scaled log2e/8); all fp16 outputs.
// ---------------------------------------------------------------------------
__global__ __launch_bounds__(256) void proj_kernel(
    const float* __restrict__ field, const float* __restrict__ query,
    const float* __restrict__ W_fk, const float* __restrict__ b_fk,
    const float* __restrict__ W_fv, const float* __restrict__ b_fv,
    const float* __restrict__ W_qk, const float* __restrict__ b_qk)
{
    extern __shared__ __align__(16) char psm[];
    float* Wh = (float*)psm;
    float* bs = (float*)(psm + OFF_BS);

    const int z = blockIdx.z, b = blockIdx.y;
    const int tid = threadIdx.x, lane = tid & 31, warp = tid >> 5;
    const int gid = lane >> 2, tig = lane & 3;

    const float *W, *bias, *X;
    switch (z) {
        case 0:  W = W_fk; bias = b_fk; X = field; break;
        case 1:  W = W_fv; bias = b_fv; X = field; break;
        default: W = W_qk; bias = b_qk; X = query; break;
    }

    for (int i = tid; i < NK * NF; i += 256) {
        int k = i >> 7, c = i & 127;
        Wh[k * WPITCH + c] = __uint_as_float(to_tf32(W[i]));
    }
    if (tid < NK) bs[tid] = bias[tid];
    __syncthreads();

    const int l0 = blockIdx.x * 256 + warp * 32;
    const uint32_t sbW = smem_u32(psm);
    const uint32_t abase =
        (uint32_t)((((lane >> 3) & 1) * 8 + (lane & 7)) * WPITCH) * 4 +
        (uint32_t)(lane >> 4) * 16;

    float acc[4][4][4];
    #pragma unroll
    for (int mt = 0; mt < 4; mt++)
        #pragma unroll
        for (int ng = 0; ng < 4; ng++)
            #pragma unroll
            for (int i = 0; i < 4; i++) acc[mt][ng][i] = 0.f;

    const float* Xb = X + (size_t)b * NF * LL;

    #pragma unroll 4
    for (int ch = 0; ch < 16; ch++) {
        uint32_t Ah[4][4];
        #pragma unroll
        for (int mt = 0; mt < 4; mt++)
            ldsm4(Ah[mt], sbW + abase + mt * (16 * WPITCH * 4) + ch * 32);
        #pragma unroll
        for (int ng = 0; ng < 4; ng++) {
            const float* xp = Xb + (size_t)(ch * 8 + tig) * LL + l0 + ng * 8 + gid;
            uint32_t b0 = to_tf32(xp[0]);
            uint32_t b1 = to_tf32(xp[4 * LL]);
            #pragma unroll
            for (int mt = 0; mt < 4; mt++)
                mma1688(acc[mt][ng], Ah[mt], b0, b1);
        }
    }

    #pragma unroll
    for (int mt = 0; mt < 4; mt++) {
        float bv0 = bs[mt * 16 + gid], bv1 = bs[mt * 16 + 8 + gid];
        #pragma unroll
        for (int ng = 0; ng < 4; ng++) {
            acc[mt][ng][0] += bv0; acc[mt][ng][1] += bv0;
            acc[mt][ng][2] += bv1; acc[mt][ng][3] += bv1;
        }
    }

    __syncthreads();
    float* stg = (float*)psm;    // [64 k][STGPITCH l]
    #pragma unroll
    for (int mt = 0; mt < 4; mt++)
        #pragma unroll
        for (int ng = 0; ng < 4; ng++) {
            int lc = warp * 32 + ng * 8 + 2 * tig;
            int k = mt * 16 + gid;
            stg[k * STGPITCH + lc]           = acc[mt][ng][0];
            stg[k * STGPITCH + lc + 1]       = acc[mt][ng][1];
            stg[(k + 8) * STGPITCH + lc]     = acc[mt][ng][2];
            stg[(k + 8) * STGPITCH + lc + 1] = acc[mt][ng][3];
        }
    __syncthreads();
    int l = blockIdx.x * 256 + tid;
    const float sc = (z == 2) ? 0.125f * 1.44269504088896f : 1.0f;
    uint32_t hw[32];
    #pragma unroll
    for (int j = 0; j < 32; j++)
        hw[j] = packf16(sc * stg[(2 * j) * STGPITCH + tid],
                        sc * stg[(2 * j + 1) * STGPITCH + tid]);
    __half* dh = (z == 0 ? g_fk : (z == 1 ? g_fv : g_hq)) +
                 ((size_t)b * LL + l) * NK;
    #pragma unroll
    for (int i = 0; i < 8; i++) ((uint4*)dh)[i] = ((uint4*)hw)[i];
}

// ---------------------------------------------------------------------------
// Kernel B: flash attention, fp16, compute-pipelined with 3-stage buffers:
// iter t: issue G(t+2); exp(s_t); wait G(t+1) (>=1 full iter of slack);
// MMA1(t+1); MMA2(t). 256 threads, 8 warps (32q x 64l per warp).
// ---------------------------------------------------------------------------
__global__ __launch_bounds__(256, 1) void attn_kernel(float* __restrict__ out)
{
    extern __shared__ __align__(16) char sm[];
    const uint32_t sb = smem_u32(sm);

    const int tid = threadIdx.x;
    const int lane = tid & 31, warp = tid >> 5;
    const int gid = lane >> 2, tig = lane & 3;
    const int wc = warp & 1, wr = warp >> 1;
    const int qw = wr * 32;
    const int b = blockIdx.y;
    const int qbase = blockIdx.x * TQ;

    const uint32_t aoff =
        (uint32_t)(qw + ((lane >> 3) & 1) * 8 + (lane & 7)) * ROWB +
        (uint32_t)(lane >> 4) * 16;
    const uint32_t b1off =
        (uint32_t)(wc * 64 + ((lane >> 3) & 1) * 8 + (lane & 7)) * ROWB +
        (uint32_t)(lane >> 4) * 16;
    const uint32_t b2off =
        (uint32_t)(wc * 64 + (lane >> 4) * 8 + (lane & 7)) * ROWB +
        (uint32_t)((lane >> 3) & 1) * 16;

    const __half* hq_g = g_hq + ((size_t)b * LL + qbase) * NK;
    const __half* fk_g = g_fk + (size_t)b * LL * NK;
    const __half* fv_g = g_fv + (size_t)b * LL * NV;

    // ---- prologue: G0 = {hq, fk0, fv0} ; G1 = {fk1, fv1} ----
    for (int i = tid; i < 1024; i += 256) {
        int row = i >> 3, c = i & 7;
        cpasync16(sb + OFF_HQ + row * ROWB + c * 16, hq_g + row * NK + c * 8);
        cpasync16(sb + OFF_FKB + row * ROWB + c * 16, fk_g + row * NK + c * 8);
        cpasync16(sb + OFF_FVB + row * ROWB + c * 16, fv_g + row * NV + c * 8);
    }
    CP_COMMIT();
    for (int i = tid; i < 1024; i += 256) {
        int row = i >> 3, c = i & 7;
        cpasync16(sb + OFF_FKB + TILESZ + row * ROWB + c * 16,
                  fk_g + (size_t)TL * NK + row * NK + c * 8);
        cpasync16(sb + OFF_FVB + TILESZ + row * ROWB + c * 16,
                  fv_g + (size_t)TL * NV + row * NV + c * 8);
    }
    CP_COMMIT();

    const uint32_t hq_b = sb + OFF_HQ + aoff;

    float y[2][8][4];
    #pragma unroll
    for (int m = 0; m < 2; m++)
        #pragma unroll
        for (int j = 0; j < 8; j++)
            #pragma unroll
            for (int i = 0; i < 4; i++) y[m][j][i] = 0.f;
    float dnacc[2][4];
    #pragma unroll
    for (int m = 0; m < 2; m++)
        #pragma unroll
        for (int i = 0; i < 4; i++) dnacc[m][i] = 0.f;

    float s[2][8][4];

    // ---- MMA1(tile 0) in prologue ----
    CP_WAIT(1);
    __syncthreads();
    {
        #pragma unroll
        for (int m = 0; m < 2; m++)
            #pragma unroll
            for (int j = 0; j < 8; j++)
                #pragma unroll
                for (int i = 0; i < 4; i++) s[m][j][i] = 0.f;
        const uint32_t fk_b = sb + OFF_FKB + b1off;
        #pragma unroll
        for (int c = 0; c < 4; c++) {
            uint32_t A0[4], A1[4];
            ldsm4(A0, hq_b + c * 32);
            ldsm4(A1, hq_b + 16 * ROWB + c * 32);
            #pragma unroll
            for (int jj = 0; jj < 4; jj++) {
                uint32_t Bk[4];
                ldsm4(Bk, fk_b + jj * (16 * ROWB) + c * 32);
                mma16816f(s[0][2 * jj],     A0, Bk[0], Bk[2]);
                mma16816f(s[0][2 * jj + 1], A0, Bk[1], Bk[3]);
                mma16816f(s[1][2 * jj],     A1, Bk[0], Bk[2]);
                mma16816f(s[1][2 * jj + 1], A1, Bk[1], Bk[3]);
            }
        }
    }

    int buf_t = 0;   // t % 3
    for (int t = 0; t < NT; ++t) {
        const int buf_n  = (buf_t == 2) ? 0 : buf_t + 1;   // (t+1) % 3
        const int buf_p  = (buf_n == 2) ? 0 : buf_n + 1;   // (t+2) % 3

        // ---- issue G(t+2) into buf (t+2)%3 (freed by end of iter t-1) ----
        if (t + 2 < NT) {
            const __half* fkt = fk_g + (size_t)(t + 2) * TL * NK;
            const __half* fvt = fv_g + (size_t)(t + 2) * TL * NV;
            const uint32_t dkb = sb + OFF_FKB + buf_p * TILESZ;
            const uint32_t dvb = sb + OFF_FVB + buf_p * TILESZ;
            for (int i = tid; i < 1024; i += 256) {
                int row = i >> 3, c = i & 7;
                cpasync16(dkb + row * ROWB + c * 16, fkt + row * NK + c * 8);
                cpasync16(dvb + row * ROWB + c * 16, fvt + row * NV + c * 8);
            }
            CP_COMMIT();
        }

        // ---- epilogue of tile t: w = exp2(s) (s completed last iter) ----
        uint32_t wf[2][8][2];
        #pragma unroll
        for (int m = 0; m < 2; m++)
            #pragma unroll
            for (int j = 0; j < 8; j++) {
                wf[m][j][0] = ex2h2(packf16(s[m][j][0], s[m][j][1]));
                wf[m][j][1] = ex2h2(packf16(s[m][j][2], s[m][j][3]));
            }

        // ---- MMA1(t+1): wait G(t+1) (committed 2 iters ago) ----
        if (t + 1 < NT) {
            if (t + 2 < NT) { CP_WAIT(1); } else { CP_WAIT(0); }
            __syncthreads();
            #pragma unroll
            for (int m = 0; m < 2; m++)
                #pragma unroll
                for (int j = 0; j < 8; j++)
                    #pragma unroll
                    for (int i = 0; i < 4; i++) s[m][j][i] = 0.f;
            const uint32_t fk_b = sb + OFF_FKB + buf_n * TILESZ + b1off;
            #pragma unroll
            for (int c = 0; c < 4; c++) {
                uint32_t A0[4], A1[4];
                ldsm4(A0, hq_b + c * 32);
                ldsm4(A1, hq_b + 16 * ROWB + c * 32);
                #pragma unroll
                for (int jj = 0; jj < 4; jj++) {
                    uint32_t Bk[4];
                    ldsm4(Bk, fk_b + jj * (16 * ROWB) + c * 32);
                    mma16816f(s[0][2 * jj],     A0, Bk[0], Bk[2]);
                    mma16816f(s[0][2 * jj + 1], A0, Bk[1], Bk[3]);
                    mma16816f(s[1][2 * jj],     A1, Bk[0], Bk[2]);
                    mma16816f(s[1][2 * jj + 1], A1, Bk[1], Bk[3]);
                }
            }
        }

        // ---- MMA2(t): Y += w * fv; denom via ones-MMA ----
        {
            const uint32_t fv_b = sb + OFF_FVB + buf_t * TILESZ + b2off;
            #pragma unroll
            for (int cc = 0; cc < 4; cc++) {
                uint32_t W0[4] = { wf[0][2 * cc][0], wf[0][2 * cc][1],
                                   wf[0][2 * cc + 1][0], wf[0][2 * cc + 1][1] };
                uint32_t W1[4] = { wf[1][2 * cc][0], wf[1][2 * cc][1],
                                   wf[1][2 * cc + 1][0], wf[1][2 * cc + 1][1] };
                mma16816f(dnacc[0], W0, ONES2, ONES2);
                mma16816f(dnacc[1], W1, ONES2, ONES2);
                #pragma unroll
                for (int jj = 0; jj < 4; jj++) {
                    uint32_t Vh[4];
                    ldsm4t(Vh, fv_b + cc * (16 * ROWB) + jj * 32);
                    mma16816f(y[0][2 * jj],     W0, Vh[0], Vh[2]);
                    mma16816f(y[0][2 * jj + 1], W0, Vh[1], Vh[3]);
                    mma16816f(y[1][2 * jj],     W1, Vh[0], Vh[2]);
                    mma16816f(y[1][2 * jj + 1], W1, Vh[1], Vh[3]);
                }
            }
        }

        __syncthreads();   // all warps done reading this iter's buffers
        buf_t = buf_n;
    }

    // ---- final reductions ----
    float* den = (float*)(sm + OFF_DEN);
    if (tig == 0) {
        #pragma unroll
        for (int m = 0; m < 2; m++) {
            den[wc * 128 + qw + m * 16 + gid]     = dnacc[m][0];
            den[wc * 128 + qw + m * 16 + 8 + gid] = dnacc[m][2];
        }
    }

    float* ysf = (float*)(sm + OFF_YS);  // [128 q][68]
    if (wc == 0) {
        #pragma unroll
        for (int m = 0; m < 2; m++)
            #pragma unroll
            for (int j = 0; j < 8; j++)
                #pragma unroll
                for (int i = 0; i < 4; i++) {
                    int q = qw + m * 16 + gid + (i >> 1) * 8;
                    int v = 8 * j + 2 * tig + (i & 1);
                    ysf[q * 68 + v] = y[m][j][i];
                }
    }
    __syncthreads();
    if (wc == 1) {
        #pragma unroll
        for (int m = 0; m < 2; m++)
            #pragma unroll
            for (int j = 0; j < 8; j++)
                #pragma unroll
                for (int i = 0; i < 4; i++) {
                    int q = qw + m * 16 + gid + (i >> 1) * 8;
                    int v = 8 * j + 2 * tig + (i & 1);
                    ysf[q * 68 + v] += y[m][j][i];
                }
    }
    __syncthreads();
    if (tid < 128)
        den[tid] = 1.0f / (den[tid] + den[128 + tid] + 1e-16f);
    __syncthreads();

    #pragma unroll
    for (int it = 0; it < 32; it++) {
        int idx = tid + it * 256;
        int v = idx >> 7, q = idx & 127;
        out[((size_t)b * NV + v) * LL + qbase + q] = ysf[q * 68 + v] * den[q];
    }
}

// ---------------------------------------------------------------------------
extern "C" void kernel_launch(void* const* d_in, const int* in_sizes, int n_in,
                              void* d_out, int out_size)
{
    const float* field = (const float*)d_in[0];
    const float* query = (const float*)d_in[1];
    const float* W_fk  = (const float*)d_in[2];
    const float* b_fk  = (const float*)d_in[3];
    const float* W_fv  = (const float*)d_in[4];
    const float* b_fv  = (const float*)d_in[5];
    const float* W_qk  = (const float*)d_in[6];
    const float* b_qk  = (const float*)d_in[7];
    float* out = (float*)d_out;

    static int configured = 0;
    if (!configured) {
        cudaFuncSetAttribute(attn_kernel,
                             cudaFuncAttributeMaxDynamicSharedMemorySize,
                             SMEM_ATTN);
        cudaFuncSetAttribute(proj_kernel,
                             cudaFuncAttributeMaxDynamicSharedMemorySize,
                             SMEM_PROJ);
        configured = 1;
    }

    dim3 gproj(LL / 256, BB, 3);
    proj_kernel<<<gproj, 256, SMEM_PROJ>>>(field, query, W_fk, b_fk,
                                           W_fv, b_fv, W_qk, b_qk);

    dim3 gattn(LL / TQ, BB);  // 32 x 4 = 128 CTAs
    attn_kernel<<<gattn, 256, SMEM_ATTN>>>(out);
}

// round 17
// speedup vs baseline: 1.1632x; 1.0768x over previous
#include <cuda_runtime.h>
#include <cuda_fp16.h>
#include <cstdint>

#define BB 4
#define NF 128
#define NK 64
#define NV 64
#define LL 4096
#define TQ 128
#define TL 128
#define NT (LL / TL)

// all attn tiles: 128 rows x 64 x 2B, row pitch 144B
#define ROWB 144
#define TILESZ 18432

#define OFF_HQ 0
#define OFF_FKB TILESZ                        // 2 bufs
#define FKBUFSZ TILESZ
#define OFF_FVB (OFF_FKB + 2 * FKBUFSZ)       // 2 bufs
#define FVBUFSZ TILESZ
#define OFF_DEN (OFF_FVB + 2 * FVBUFSZ)       // float[2][128]
#define SMEM_ATTN (OFF_DEN + 1024)            // 93184
#define OFF_YS OFF_FKB                        // reuse post-loop: float[128][68]

// ---- proj smem ----
#define WPITCH 132
#define WTILE (64 * WPITCH * 4)
#define OFF_BS WTILE
#define STGPITCH 260
#define SMEM_PROJ (2 * WTILE + 512)

#define ONES2 0x3C003C00u   // f16x2 (1.0, 1.0)

// projection outputs, all fp16 [b][row][64]:
// hq (pre-scaled by log2e/8), fk, fv
__device__ __align__(256) __half g_hq[BB * LL * NK];
__device__ __align__(256) __half g_fk[BB * LL * NK];
__device__ __align__(256) __half g_fv[BB * LL * NV];

// ---------------------------------------------------------------------------
__device__ __forceinline__ uint32_t smem_u32(const void* p) {
    uint32_t a;
    asm("{ .reg .u64 t; cvta.to.shared.u64 t, %1; cvt.u32.u64 %0, t; }"
        : "=r"(a) : "l"(p));
    return a;
}
__device__ __forceinline__ void cpasync16(uint32_t dst, const void* src) {
    asm volatile("cp.async.cg.shared.global [%0], [%1], 16;"
                 :: "r"(dst), "l"(src));
}
#define CP_COMMIT() asm volatile("cp.async.commit_group;")
#define CP_WAIT(n)  asm volatile("cp.async.wait_group %0;" :: "n"(n))

__device__ __forceinline__ void ldsm4(uint32_t* r, uint32_t a) {
    asm volatile("ldmatrix.sync.aligned.m8n8.x4.shared.b16 {%0,%1,%2,%3}, [%4];"
        : "=r"(r[0]), "=r"(r[1]), "=r"(r[2]), "=r"(r[3]) : "r"(a));
}
__device__ __forceinline__ void ldsm4t(uint32_t* r, uint32_t a) {
    asm volatile("ldmatrix.sync.aligned.m8n8.x4.trans.shared.b16 {%0,%1,%2,%3}, [%4];"
        : "=r"(r[0]), "=r"(r[1]), "=r"(r[2]), "=r"(r[3]) : "r"(a));
}
// fp16 MMA
__device__ __forceinline__ void mma16816f(
    float* d, const uint32_t* a, uint32_t b0, uint32_t b1)
{
    asm volatile(
        "mma.sync.aligned.m16n8k16.row.col.f32.f16.f16.f32 "
        "{%0,%1,%2,%3}, {%4,%5,%6,%7}, {%8,%9}, {%0,%1,%2,%3};"
        : "+f"(d[0]), "+f"(d[1]), "+f"(d[2]), "+f"(d[3])
        : "r"(a[0]), "r"(a[1]), "r"(a[2]), "r"(a[3]), "r"(b0), "r"(b1));
}
// tf32 MMA (proj only)
__device__ __forceinline__ void mma1688(
    float* d, const uint32_t* a, uint32_t b0, uint32_t b1)
{
    asm volatile(
        "mma.sync.aligned.m16n8k8.row.col.f32.tf32.tf32.f32 "
        "{%0,%1,%2,%3}, {%4,%5,%6,%7}, {%8,%9}, {%0,%1,%2,%3};"
        : "+f"(d[0]), "+f"(d[1]), "+f"(d[2]), "+f"(d[3])
        : "r"(a[0]), "r"(a[1]), "r"(a[2]), "r"(a[3]), "r"(b0), "r"(b1));
}
__device__ __forceinline__ uint32_t to_tf32(float x) {
    uint32_t r;
    asm("cvt.rna.tf32.f32 %0, %1;" : "=r"(r) : "f"(x));
    return r;
}
__device__ __forceinline__ uint32_t packf16(float x0, float x1) {
    uint32_t p;
    asm("cvt.rn.f16x2.f32 %0, %1, %2;" : "=r"(p) : "f"(x1), "f"(x0));
    return p;
}
__device__ __forceinline__ uint32_t ex2h2(uint32_t x) {
    uint32_t r;
    asm("ex2.approx.f16x2 %0, %1;" : "=r"(r) : "r"(x));
    return r;
}

// ---------------------------------------------------------------------------
// Kernel A: projections via single-term tf32 tensor cores (R15, unchanged).
// z=0 fk, z=1 fv, z=2 hq (scaled log2e/8); all fp16 outputs.
// ---------------------------------------------------------------------------
__global__ __launch_bounds__(256) void proj_kernel(
    const float* __restrict__ field, const float* __restrict__ query,
    const float* __restrict__ W_fk, const float* __restrict__ b_fk,
    const float* __restrict__ W_fv, const float* __restrict__ b_fv,
    const float* __restrict__ W_qk, const float* __restrict__ b_qk)
{
    extern __shared__ __align__(16) char psm[];
    float* Wh = (float*)psm;
    float* bs = (float*)(psm + OFF_BS);

    const int z = blockIdx.z, b = blockIdx.y;
    const int tid = threadIdx.x, lane = tid & 31, warp = tid >> 5;
    const int gid = lane >> 2, tig = lane & 3;

    const float *W, *bias, *X;
    switch (z) {
        case 0:  W = W_fk; bias = b_fk; X = field; break;
        case 1:  W = W_fv; bias = b_fv; X = field; break;
        default: W = W_qk; bias = b_qk; X = query; break;
    }

    for (int i = tid; i < NK * NF; i += 256) {
        int k = i >> 7, c = i & 127;
        Wh[k * WPITCH + c] = __uint_as_float(to_tf32(W[i]));
    }
    if (tid < NK) bs[tid] = bias[tid];
    __syncthreads();

    const int l0 = blockIdx.x * 256 + warp * 32;
    const uint32_t sbW = smem_u32(psm);
    const uint32_t abase =
        (uint32_t)((((lane >> 3) & 1) * 8 + (lane & 7)) * WPITCH) * 4 +
        (uint32_t)(lane >> 4) * 16;

    float acc[4][4][4];
    #pragma unroll
    for (int mt = 0; mt < 4; mt++)
        #pragma unroll
        for (int ng = 0; ng < 4; ng++)
            #pragma unroll
            for (int i = 0; i < 4; i++) acc[mt][ng][i] = 0.f;

    const float* Xb = X + (size_t)b * NF * LL;

    #pragma unroll 4
    for (int ch = 0; ch < 16; ch++) {
        uint32_t Ah[4][4];
        #pragma unroll
        for (int mt = 0; mt < 4; mt++)
            ldsm4(Ah[mt], sbW + abase + mt * (16 * WPITCH * 4) + ch * 32);
        #pragma unroll
        for (int ng = 0; ng < 4; ng++) {
            const float* xp = Xb + (size_t)(ch * 8 + tig) * LL + l0 + ng * 8 + gid;
            uint32_t b0 = to_tf32(xp[0]);
            uint32_t b1 = to_tf32(xp[4 * LL]);
            #pragma unroll
            for (int mt = 0; mt < 4; mt++)
                mma1688(acc[mt][ng], Ah[mt], b0, b1);
        }
    }

    #pragma unroll
    for (int mt = 0; mt < 4; mt++) {
        float bv0 = bs[mt * 16 + gid], bv1 = bs[mt * 16 + 8 + gid];
        #pragma unroll
        for (int ng = 0; ng < 4; ng++) {
            acc[mt][ng][0] += bv0; acc[mt][ng][1] += bv0;
            acc[mt][ng][2] += bv1; acc[mt][ng][3] += bv1;
        }
    }

    __syncthreads();
    float* stg = (float*)psm;    // [64 k][STGPITCH l]
    #pragma unroll
    for (int mt = 0; mt < 4; mt++)
        #pragma unroll
        for (int ng = 0; ng < 4; ng++) {
            int lc = warp * 32 + ng * 8 + 2 * tig;
            int k = mt * 16 + gid;
            stg[k * STGPITCH + lc]           = acc[mt][ng][0];
            stg[k * STGPITCH + lc + 1]       = acc[mt][ng][1];
            stg[(k + 8) * STGPITCH + lc]     = acc[mt][ng][2];
            stg[(k + 8) * STGPITCH + lc + 1] = acc[mt][ng][3];
        }
    __syncthreads();
    int l = blockIdx.x * 256 + tid;
    const float sc = (z == 2) ? 0.125f * 1.44269504088896f : 1.0f;
    uint32_t hw[32];
    #pragma unroll
    for (int j = 0; j < 32; j++)
        hw[j] = packf16(sc * stg[(2 * j) * STGPITCH + tid],
                        sc * stg[(2 * j + 1) * STGPITCH + tid]);
    __half* dh = (z == 0 ? g_fk : (z == 1 ? g_fv : g_hq)) +
                 ((size_t)b * LL + l) * NK;
    #pragma unroll
    for (int i = 0; i < 8; i++) ((uint4*)dh)[i] = ((uint4*)hw)[i];
}

// ---------------------------------------------------------------------------
// Kernel B: flash attention (exact R12 structure — best measured: 65.9 us).
// 256 threads, 8 warps, warp tile 32q x 64l; fp16 MMA1 + MMA2; f16x2 exp;
// ones-MMA denominator; double-buffered cp.async with full-iteration slack.
// ---------------------------------------------------------------------------
__global__ __launch_bounds__(256, 1) void attn_kernel(float* __restrict__ out)
{
    extern __shared__ __align__(16) char sm[];
    const uint32_t sb = smem_u32(sm);

    const int tid = threadIdx.x;
    const int lane = tid & 31, warp = tid >> 5;
    const int gid = lane >> 2, tig = lane & 3;
    const int wc = warp & 1, wr = warp >> 1;
    const int qw = wr * 32;
    const int b = blockIdx.y;
    const int qbase = blockIdx.x * TQ;

    const uint32_t aoff =
        (uint32_t)(qw + ((lane >> 3) & 1) * 8 + (lane & 7)) * ROWB +
        (uint32_t)(lane >> 4) * 16;
    const uint32_t b1off =
        (uint32_t)(wc * 64 + ((lane >> 3) & 1) * 8 + (lane & 7)) * ROWB +
        (uint32_t)(lane >> 4) * 16;
    const uint32_t b2off =
        (uint32_t)(wc * 64 + (lane >> 4) * 8 + (lane & 7)) * ROWB +
        (uint32_t)((lane >> 3) & 1) * 16;

    const __half* hq_g = g_hq + ((size_t)b * LL + qbase) * NK;
    const __half* fk_g = g_fk + (size_t)b * LL * NK;
    const __half* fv_g = g_fv + (size_t)b * LL * NV;

    // ---- prologue: hq tile + field tile 0 ----
    for (int i = tid; i < 1024; i += 256) {
        int row = i >> 3, c = i & 7;
        cpasync16(sb + OFF_HQ + row * ROWB + c * 16, hq_g + row * NK + c * 8);
        cpasync16(sb + OFF_FKB + row * ROWB + c * 16, fk_g + row * NK + c * 8);
        cpasync16(sb + OFF_FVB + row * ROWB + c * 16, fv_g + row * NV + c * 8);
    }
    CP_COMMIT();

    float y[2][8][4];
    #pragma unroll
    for (int m = 0; m < 2; m++)
        #pragma unroll
        for (int j = 0; j < 8; j++)
            #pragma unroll
            for (int i = 0; i < 4; i++) y[m][j][i] = 0.f;
    float dnacc[2][4];
    #pragma unroll
    for (int m = 0; m < 2; m++)
        #pragma unroll
        for (int i = 0; i < 4; i++) dnacc[m][i] = 0.f;

    for (int t = 0; t < NT; ++t) {
        if (t + 1 < NT) {
            __syncthreads();
            int buf = (t + 1) & 1;
            const __half* fkt = fk_g + (size_t)(t + 1) * TL * NK;
            const __half* fvt = fv_g + (size_t)(t + 1) * TL * NV;
            for (int i = tid; i < 1024; i += 256) {
                int row = i >> 3, c = i & 7;
                cpasync16(sb + OFF_FKB + buf * FKBUFSZ + row * ROWB + c * 16,
                          fkt + row * NK + c * 8);
                cpasync16(sb + OFF_FVB + buf * FVBUFSZ + row * ROWB + c * 16,
                          fvt + row * NV + c * 8);
            }
            CP_COMMIT();
            CP_WAIT(1);
        } else {
            CP_WAIT(0);
        }
        __syncthreads();

        const int buf = t & 1;
        const uint32_t hq_b = sb + OFF_HQ + aoff;
        const uint32_t fk_b = sb + OFF_FKB + buf * FKBUFSZ + b1off;
        const uint32_t fv_b = sb + OFF_FVB + buf * FVBUFSZ + b2off;

        // ---- MMA1 (fp16): S[32 q][64 l], K = 64 (4 k16 chunks) ----
        float s[2][8][4];
        #pragma unroll
        for (int m = 0; m < 2; m++)
            #pragma unroll
            for (int j = 0; j < 8; j++)
                #pragma unroll
                for (int i = 0; i < 4; i++) s[m][j][i] = 0.f;

        #pragma unroll
        for (int c = 0; c < 4; c++) {
            uint32_t A0[4], A1[4];
            ldsm4(A0, hq_b + c * 32);
            ldsm4(A1, hq_b + 16 * ROWB + c * 32);
            #pragma unroll
            for (int jj = 0; jj < 4; jj++) {
                uint32_t Bk[4];
                ldsm4(Bk, fk_b + jj * (16 * ROWB) + c * 32);
                mma16816f(s[0][2 * jj],     A0, Bk[0], Bk[2]);
                mma16816f(s[0][2 * jj + 1], A0, Bk[1], Bk[3]);
                mma16816f(s[1][2 * jj],     A1, Bk[0], Bk[2]);
                mma16816f(s[1][2 * jj + 1], A1, Bk[1], Bk[3]);
            }
        }

        // ---- epilogue: w = exp2(s) via f16x2, packed as A-fragments ----
        uint32_t wf[2][8][2];
        #pragma unroll
        for (int m = 0; m < 2; m++)
            #pragma unroll
            for (int j = 0; j < 8; j++) {
                wf[m][j][0] = ex2h2(packf16(s[m][j][0], s[m][j][1]));
                wf[m][j][1] = ex2h2(packf16(s[m][j][2], s[m][j][3]));
            }

        // ---- MMA2 (fp16): Y[32 q][64 v] += w * fv; denom via ones-MMA ----
        #pragma unroll
        for (int cc = 0; cc < 4; cc++) {
            uint32_t W0[4] = { wf[0][2 * cc][0], wf[0][2 * cc][1],
                               wf[0][2 * cc + 1][0], wf[0][2 * cc + 1][1] };
            uint32_t W1[4] = { wf[1][2 * cc][0], wf[1][2 * cc][1],
                               wf[1][2 * cc + 1][0], wf[1][2 * cc + 1][1] };
            mma16816f(dnacc[0], W0, ONES2, ONES2);
            mma16816f(dnacc[1], W1, ONES2, ONES2);
            #pragma unroll
            for (int jj = 0; jj < 4; jj++) {
                uint32_t Vh[4];
                ldsm4t(Vh, fv_b + cc * (16 * ROWB) + jj * 32);
                mma16816f(y[0][2 * jj],     W0, Vh[0], Vh[2]);
                mma16816f(y[0][2 * jj + 1], W0, Vh[1], Vh[3]);
                mma16816f(y[1][2 * jj],     W1, Vh[0], Vh[2]);
                mma16816f(y[1][2 * jj + 1], W1, Vh[1], Vh[3]);
            }
        }
    }

    // ---- final reductions ----
    __syncthreads();  // done with fk buffers (ysf aliases them)

    float* den = (float*)(sm + OFF_DEN);
    if (tig == 0) {
        #pragma unroll
        for (int m = 0; m < 2; m++) {
            den[wc * 128 + qw + m * 16 + gid]     = dnacc[m][0];
            den[wc * 128 + qw + m * 16 + 8 + gid] = dnacc[m][2];
        }
    }

    float* ysf = (float*)(sm + OFF_YS);  // [128 q][68]
    if (wc == 0) {
        #pragma unroll
        for (int m = 0; m < 2; m++)
            #pragma unroll
            for (int j = 0; j < 8; j++)
                #pragma unroll
                for (int i = 0; i < 4; i++) {
                    int q = qw + m * 16 + gid + (i >> 1) * 8;
                    int v = 8 * j + 2 * tig + (i & 1);
                    ysf[q * 68 + v] = y[m][j][i];
                }
    }
    __syncthreads();
    if (wc == 1) {
        #pragma unroll
        for (int m = 0; m < 2; m++)
            #pragma unroll
            for (int j = 0; j < 8; j++)
                #pragma unroll
                for (int i = 0; i < 4; i++) {
                    int q = qw + m * 16 + gid + (i >> 1) * 8;
                    int v = 8 * j + 2 * tig + (i & 1);
                    ysf[q * 68 + v] += y[m][j][i];
                }
    }
    __syncthreads();
    if (tid < 128)
        den[tid] = 1.0f / (den[tid] + den[128 + tid] + 1e-16f);
    __syncthreads();

    #pragma unroll
    for (int it = 0; it < 32; it++) {
        int idx = tid + it * 256;
        int v = idx >> 7, q = idx & 127;
        out[((size_t)b * NV + v) * LL + qbase + q] = ysf[q * 68 + v] * den[q];
    }
}

// ---------------------------------------------------------------------------
extern "C" void kernel_launch(void* const* d_in, const int* in_sizes, int n_in,
                              void* d_out, int out_size)
{
    const float* field = (const float*)d_in[0];
    const float* query = (const float*)d_in[1];
    const float* W_fk  = (const float*)d_in[2];
    const float* b_fk  = (const float*)d_in[3];
    const float* W_fv  = (const float*)d_in[4];
    const float* b_fv  = (const float*)d_in[5];
    const float* W_qk  = (const float*)d_in[6];
    const float* b_qk  = (const float*)d_in[7];
    float* out = (float*)d_out;

    static int configured = 0;
    if (!configured) {
        cudaFuncSetAttribute(attn_kernel,
                             cudaFuncAttributeMaxDynamicSharedMemorySize,
                             SMEM_ATTN);
        cudaFuncSetAttribute(proj_kernel,
                             cudaFuncAttributeMaxDynamicSharedMemorySize,
                             SMEM_PROJ);
        configured = 1;
    }

    dim3 gproj(LL / 256, BB, 3);
    proj_kernel<<<gproj, 256, SMEM_PROJ>>>(field, query, W_fk, b_fk,
                                           W_fv, b_fv, W_qk, b_qk);

    dim3 gattn(LL / TQ, BB);  // 32 x 4 = 128 CTAs
    attn_kernel<<<gattn, 256, SMEM_ATTN>>>(out);
}